// round 11
// baseline (speedup 1.0000x reference)
#include <cuda_runtime.h>
#include <cuda_bf16.h>
#include <cuda_fp16.h>
#include <mma.h>
#include <cstdint>

using namespace nvcuda;

#define B_SZ 65536
#define D_SZ 256
#define F_SZ 512
#define P_SZ 256

// padded smem strides — all row strides odd in 16B units => conflict-free
#define RS_LD  520   // bf16: 1040B = 65 units
#define XS_LD  264   // fp16: 528B  = 33 units
#define OS_LD  260   // fp32: 1040B = 65 units
#define PS_LD  260   // pside fp32

// ---------------- scratch (static device globals; no allocations) ----------------
__device__ __nv_bfloat16 g_W1[P_SZ * F_SZ];   // theta*pw + alpha*pp
__device__ __nv_bfloat16 g_W2[P_SZ * F_SZ];   // beta*pw
__device__ float         g_biasP[P_SZ];       // -beta * pws[p]
__device__ __half        g_Fh[F_SZ * D_SZ];   // features in fp16 (stage-1 B operand)

// ===================== kernel 1: p-side precompute (+ features fp32->fp16) =====================
__global__ __launch_bounds__(256, 1)
void pside_kernel(const float* __restrict__ prototypes,
                  const float* __restrict__ features,
                  const float* __restrict__ alpha,
                  const float* __restrict__ beta,
                  const float* __restrict__ theta) {
    extern __shared__ float smp[];
    float* ps   = smp;
    float* Outs = smp + 16 * PS_LD;

    int tid  = threadIdx.x;
    int warp = tid >> 5;
    int lane = tid & 31;
    int p0   = blockIdx.x * 16;

    // prologue: convert features slice to fp16 (grid-stride over 16 CTAs)
    for (int i = blockIdx.x * 256 + tid; i < F_SZ * D_SZ / 4; i += 16 * 256) {
        float4 v = ((const float4*)features)[i];
        __half2 h0 = __floats2half2_rn(v.x, v.y);
        __half2 h1 = __floats2half2_rn(v.z, v.w);
        uint2 w;
        w.x = *reinterpret_cast<uint32_t*>(&h0);
        w.y = *reinterpret_cast<uint32_t*>(&h1);
        ((uint2*)g_Fh)[i] = w;
    }

    {
        const float4* src = (const float4*)(prototypes + (size_t)p0 * D_SZ);
        for (int i = tid; i < 16 * D_SZ / 4; i += 256) {
            int row = i >> 6, q = i & 63;
            ((float4*)(ps + row * PS_LD))[q] = src[(size_t)row * 64 + q];
        }
    }
    __syncthreads();

    using FragA = wmma::fragment<wmma::matrix_a, 16, 16, 8, wmma::precision::tf32, wmma::row_major>;
    using FragB = wmma::fragment<wmma::matrix_b, 16, 16, 8, wmma::precision::tf32, wmma::col_major>;
    using FragC = wmma::fragment<wmma::accumulator, 16, 16, 8, float>;

    FragC c[4];
#pragma unroll
    for (int j = 0; j < 4; j++) wmma::fill_fragment(c[j], 0.f);

    int f0 = warp * 64;
#pragma unroll 4
    for (int k0 = 0; k0 < D_SZ; k0 += 8) {
        FragA a;
        wmma::load_matrix_sync(a, ps + k0, PS_LD);
#pragma unroll
        for (int e = 0; e < a.num_elements; e++) a.x[e] = wmma::__float_to_tf32(a.x[e]);
#pragma unroll
        for (int j = 0; j < 4; j++) {
            FragB b;
            wmma::load_matrix_sync(b, features + (size_t)(f0 + j * 16) * D_SZ + k0, D_SZ);
#pragma unroll
            for (int e = 0; e < b.num_elements; e++) b.x[e] = wmma::__float_to_tf32(b.x[e]);
            wmma::mma_sync(c[j], a, b, c[j]);
        }
    }
#pragma unroll
    for (int j = 0; j < 4; j++)
        wmma::store_matrix_sync(Outs + f0 + j * 16, c[j], F_SZ, wmma::mem_row_major);
    __syncthreads();

    float a_ = alpha[0], b_ = beta[0], th = theta[0];
    for (int i = tid; i < 16 * F_SZ; i += 256) {
        int pr = i >> 9, f = i & 511;
        float acc = Outs[i];
        float pp = fmaxf(acc, 0.f);
        float pw = acc * pp;
        g_W1[(size_t)(p0 + pr) * F_SZ + f] = __float2bfloat16(th * pw + a_ * pp);
        g_W2[(size_t)(p0 + pr) * F_SZ + f] = __float2bfloat16(b_ * pw);
    }
    for (int r = warp * 2; r < warp * 2 + 2; r++) {
        float s = 0.f;
        for (int cix = lane; cix < F_SZ; cix += 32) {
            float acc = Outs[r * F_SZ + cix];
            s += acc * fmaxf(acc, 0.f);
        }
#pragma unroll
        for (int o = 16; o > 0; o >>= 1) s += __shfl_xor_sync(0xffffffffu, s, o);
        if (lane == 0) g_biasP[p0 + r] = -b_ * s;
    }
}

// ===================== kernel 2: fused, 64-row CTAs, 2 CTA/SM =====================
#define RS_BYTES   (64 * RS_LD * 2)                  // 66,560
#define BUF_OFF    RS_BYTES
#define STWP_OFF   (BUF_OFF + 34048)
#define BUF_BYTES  (34048 + 8192)
#define RB_OFF     (BUF_OFF + BUF_BYTES)
#define BP_OFF     (RB_OFF + 256)
#define SMEM_FUSED (BP_OFF + 1024)                   // ≈ 107 KB

__global__ __launch_bounds__(256, 2)
void fused_kernel(const float* __restrict__ x,
                  const float* __restrict__ alpha,
                  float* __restrict__ out) {
    extern __shared__ char smraw[];
    __nv_bfloat16* Rs = (__nv_bfloat16*)smraw;
    float*         rb = (float*)(smraw + RB_OFF);
    float*         bp = (float*)(smraw + BP_OFF);

    int tid  = threadIdx.x;
    int warp = tid >> 5;
    int lane = tid & 31;
    int m0   = blockIdx.x * 64;

    // ---------------- Phase A: R = relu(x @ F^T), fp16, B-frags double-buffered ----------------
    using FA1 = wmma::fragment<wmma::matrix_a, 16, 16, 16, __half, wmma::row_major>;
    using FB1 = wmma::fragment<wmma::matrix_b, 16, 16, 16, __half, wmma::col_major>;
    using FC1 = wmma::fragment<wmma::accumulator, 16, 16, 16, float>;

    __half* xs = (__half*)(smraw + BUF_OFF);   // [64][XS_LD] fp16, whole K resident
    {
        const float4* src = (const float4*)(x + (size_t)m0 * D_SZ);
        for (int i = tid; i < 64 * 64; i += 256) {
            int row = i >> 6, q = i & 63;
            float4 v = src[(size_t)row * 64 + q];
            __half2 h0 = __floats2half2_rn(v.x, v.y);
            __half2 h1 = __floats2half2_rn(v.z, v.w);
            uint2 w;
            w.x = *reinterpret_cast<uint32_t*>(&h0);
            w.y = *reinterpret_cast<uint32_t*>(&h1);
            *(uint2*)(xs + row * XS_LD + q * 4) = w;
        }
    }
    __syncthreads();

    for (int fpass = 0; fpass < 2; fpass++) {
        FC1 c[4][2];
#pragma unroll
        for (int i = 0; i < 4; i++)
#pragma unroll
            for (int j = 0; j < 2; j++) wmma::fill_fragment(c[i][j], 0.f);

        int f0 = fpass * 256 + warp * 32;

        FB1 b[2][2];   // [buf][j]
#pragma unroll
        for (int j = 0; j < 2; j++)
            wmma::load_matrix_sync(b[0][j], g_Fh + (size_t)(f0 + j * 16) * D_SZ, D_SZ);

#pragma unroll
        for (int kk = 0; kk < 16; kk++) {
            int cur = kk & 1, nxt = cur ^ 1;
            if (kk < 15) {
#pragma unroll
                for (int j = 0; j < 2; j++)
                    wmma::load_matrix_sync(b[nxt][j],
                        g_Fh + (size_t)(f0 + j * 16) * D_SZ + (kk + 1) * 16, D_SZ);
            }
#pragma unroll
            for (int i = 0; i < 4; i++) {
                FA1 a;
                wmma::load_matrix_sync(a, xs + (i * 16) * XS_LD + kk * 16, XS_LD);
#pragma unroll
                for (int j = 0; j < 2; j++) wmma::mma_sync(c[i][j], a, b[cur][j], c[i][j]);
            }
        }

        float* stw = (float*)(smraw + STWP_OFF) + warp * 256;
#pragma unroll
        for (int i = 0; i < 4; i++) {
#pragma unroll
            for (int j = 0; j < 2; j++) {
                wmma::store_matrix_sync(stw, c[i][j], 16, wmma::mem_row_major);
                __syncwarp();
#pragma unroll
                for (int e = 0; e < 8; e++) {
                    int idx = lane * 8 + e;
                    int rr = idx >> 4, cc = idx & 15;
                    float v = fmaxf(stw[idx], 0.f);
                    Rs[(i * 16 + rr) * RS_LD + f0 + j * 16 + cc] = __float2bfloat16(v);
                }
                __syncwarp();
            }
        }
    }
    __syncthreads();   // Rs complete; xs/stw dead

    // row bias
    {
        float av = alpha[0];
        for (int r = warp * 8; r < warp * 8 + 8; r++) {
            float s = 0.f;
            for (int cix = lane; cix < F_SZ; cix += 32) {
                float v = __bfloat162float(Rs[r * RS_LD + cix]);
                s += v * v;
            }
#pragma unroll
            for (int o = 16; o > 0; o >>= 1) s += __shfl_xor_sync(0xffffffffu, s, o);
            if (lane == 0) rb[r] = -av * s;
        }
    }
    if (tid < P_SZ) bp[tid] = g_biasP[tid];

    // ---------------- Phase B: out = [R^2|R] @ [W1|W2]^T, bf16, 64x32 warp tiles ----------------
    // W frags direct from global (L2), double-buffered across k. A-frag squared in place
    // between its W2 and W1 MMAs (saves the a2 array).
    using FA2 = wmma::fragment<wmma::matrix_a, 16, 16, 16, __nv_bfloat16, wmma::row_major>;
    using FB2 = wmma::fragment<wmma::matrix_b, 16, 16, 16, __nv_bfloat16, wmma::col_major>;
    using FC2 = wmma::fragment<wmma::accumulator, 16, 16, 16, float>;

    int ncol = warp * 32;

    FC2 c2[4][2];
#pragma unroll
    for (int i = 0; i < 4; i++)
#pragma unroll
        for (int j = 0; j < 2; j++) wmma::fill_fragment(c2[i][j], 0.f);

    FB2 b1[2][2], b2[2][2];   // [buf][j]
#pragma unroll
    for (int j = 0; j < 2; j++) {
        wmma::load_matrix_sync(b1[0][j], g_W1 + (size_t)(ncol + j * 16) * F_SZ, F_SZ);
        wmma::load_matrix_sync(b2[0][j], g_W2 + (size_t)(ncol + j * 16) * F_SZ, F_SZ);
    }

#pragma unroll 4
    for (int kk = 0; kk < 32; kk++) {
        int cur = kk & 1, nxt = cur ^ 1;
        if (kk < 31) {
#pragma unroll
            for (int j = 0; j < 2; j++) {
                wmma::load_matrix_sync(b1[nxt][j],
                    g_W1 + (size_t)(ncol + j * 16) * F_SZ + (kk + 1) * 16, F_SZ);
                wmma::load_matrix_sync(b2[nxt][j],
                    g_W2 + (size_t)(ncol + j * 16) * F_SZ + (kk + 1) * 16, F_SZ);
            }
        }
#pragma unroll
        for (int i = 0; i < 4; i++) {
            FA2 a;
            wmma::load_matrix_sync(a, Rs + (i * 16) * RS_LD + kk * 16, RS_LD);
            // R * W2 first
#pragma unroll
            for (int j = 0; j < 2; j++) wmma::mma_sync(c2[i][j], a, b2[cur][j], c2[i][j]);
            // square in place -> R^2 * W1
#pragma unroll
            for (int e = 0; e < a.num_elements; e++) a.x[e] = a.x[e] * a.x[e];
#pragma unroll
            for (int j = 0; j < 2; j++) wmma::mma_sync(c2[i][j], a, b1[cur][j], c2[i][j]);
        }
    }
    __syncthreads();   // all warps done reading Rs -> Os takes over the buffer

    float* Os = (float*)smraw;   // [64][OS_LD] fp32
#pragma unroll
    for (int i = 0; i < 4; i++)
#pragma unroll
        for (int j = 0; j < 2; j++)
            wmma::store_matrix_sync(Os + (i * 16) * OS_LD + ncol + j * 16, c2[i][j],
                                    OS_LD, wmma::mem_row_major);
    __syncthreads();

    for (int i = tid; i < 64 * P_SZ; i += 256) {
        int r = i >> 8;
        int p = i & 255;
        out[(size_t)(m0 + r) * P_SZ + p] = Os[r * OS_LD + p] + rb[r] + bp[p];
    }
}

// =========================== launch ===========================
extern "C" void kernel_launch(void* const* d_in, const int* in_sizes, int n_in,
                              void* d_out, int out_size) {
    const float* x          = (const float*)d_in[0];
    const float* features   = (const float*)d_in[1];
    const float* prototypes = (const float*)d_in[2];
    const float* alpha      = (const float*)d_in[3];
    const float* beta       = (const float*)d_in[4];
    const float* theta      = (const float*)d_in[5];
    float* out = (float*)d_out;

    cudaFuncSetAttribute(pside_kernel, cudaFuncAttributeMaxDynamicSharedMemorySize, 64 * 1024);
    cudaFuncSetAttribute(fused_kernel, cudaFuncAttributeMaxDynamicSharedMemorySize, SMEM_FUSED);

    pside_kernel<<<P_SZ / 16, 256, 64 * 1024>>>(prototypes, features, alpha, beta, theta);
    fused_kernel<<<B_SZ / 64, 256, SMEM_FUSED>>>(x, alpha, out);
}

// round 12
// speedup vs baseline: 1.2896x; 1.2896x over previous
#include <cuda_runtime.h>
#include <cuda_bf16.h>
#include <cuda_fp16.h>
#include <mma.h>
#include <cstdint>

using namespace nvcuda;

#define B_SZ 65536
#define D_SZ 256
#define F_SZ 512
#define P_SZ 256

// padded smem strides — all row strides odd in 16B units => conflict-free
#define RS_LD  520   // bf16: 1040B = 65 units
#define XS_LD  264   // fp16: 528B  = 33 units
#define OS_LD  260   // fp32: 1040B = 65 units
#define PS_LD  260   // pside fp32

// ---------------- scratch (static device globals; no allocations) ----------------
// W packed in mma.sync m16n8k16 B-fragment layout: [nb=P/8][kb=F/16][lane] -> uint2
// reg r of lane l holds W[n = nb*8 + l/4][k = kb*16 + (l%4)*2 + 8r .. +1] as bf16x2.
__device__ uint2  g_W1p[(P_SZ / 8) * (F_SZ / 16) * 32];
__device__ uint2  g_W2p[(P_SZ / 8) * (F_SZ / 16) * 32];
__device__ float  g_biasP[P_SZ];              // -beta * pws[p]
__device__ __half g_Fh[F_SZ * D_SZ];          // features fp16 (stage-1 B operand)

__device__ __forceinline__ uint32_t smem_u32(const void* p) {
    uint32_t a;
    asm("{ .reg .u64 t; cvta.to.shared.u64 t, %1; cvt.u32.u64 %0, t; }" : "=r"(a) : "l"(p));
    return a;
}

// ===================== kernel 0: features fp32 -> fp16 =====================
__global__ __launch_bounds__(256)
void fconv_kernel(const float* __restrict__ features) {
    int i = blockIdx.x * 256 + threadIdx.x;
    float4 v = ((const float4*)features)[i];
    __half2 h0 = __floats2half2_rn(v.x, v.y);
    __half2 h1 = __floats2half2_rn(v.z, v.w);
    uint2 w;
    w.x = *reinterpret_cast<uint32_t*>(&h0);
    w.y = *reinterpret_cast<uint32_t*>(&h1);
    ((uint2*)g_Fh)[i] = w;
}

// ===================== kernel 1: p-side precompute (tf32 wmma) =====================
__global__ __launch_bounds__(256, 1)
void pside_kernel(const float* __restrict__ prototypes,
                  const float* __restrict__ features,
                  const float* __restrict__ alpha,
                  const float* __restrict__ beta,
                  const float* __restrict__ theta) {
    extern __shared__ float smp[];
    float* ps   = smp;
    float* Outs = smp + 16 * PS_LD;

    int tid  = threadIdx.x;
    int warp = tid >> 5;
    int lane = tid & 31;
    int p0   = blockIdx.x * 16;

    {
        const float4* src = (const float4*)(prototypes + (size_t)p0 * D_SZ);
        for (int i = tid; i < 16 * D_SZ / 4; i += 256) {
            int row = i >> 6, q = i & 63;
            ((float4*)(ps + row * PS_LD))[q] = src[(size_t)row * 64 + q];
        }
    }
    __syncthreads();

    using FragA = wmma::fragment<wmma::matrix_a, 16, 16, 8, wmma::precision::tf32, wmma::row_major>;
    using FragB = wmma::fragment<wmma::matrix_b, 16, 16, 8, wmma::precision::tf32, wmma::col_major>;
    using FragC = wmma::fragment<wmma::accumulator, 16, 16, 8, float>;

    FragC c[4];
#pragma unroll
    for (int j = 0; j < 4; j++) wmma::fill_fragment(c[j], 0.f);

    int f0 = warp * 64;
#pragma unroll 4
    for (int k0 = 0; k0 < D_SZ; k0 += 8) {
        FragA a;
        wmma::load_matrix_sync(a, ps + k0, PS_LD);
#pragma unroll
        for (int e = 0; e < a.num_elements; e++) a.x[e] = wmma::__float_to_tf32(a.x[e]);
#pragma unroll
        for (int j = 0; j < 4; j++) {
            FragB b;
            wmma::load_matrix_sync(b, features + (size_t)(f0 + j * 16) * D_SZ + k0, D_SZ);
#pragma unroll
            for (int e = 0; e < b.num_elements; e++) b.x[e] = wmma::__float_to_tf32(b.x[e]);
            wmma::mma_sync(c[j], a, b, c[j]);
        }
    }
#pragma unroll
    for (int j = 0; j < 4; j++)
        wmma::store_matrix_sync(Outs + f0 + j * 16, c[j], F_SZ, wmma::mem_row_major);
    __syncthreads();

    float a_ = alpha[0], b_ = beta[0], th = theta[0];

    // pack W1/W2 fragments: this CTA covers nb blocks {blockIdx*2, blockIdx*2+1}
    // uint2 entries per CTA: 2 nb * 32 kb * 32 lanes = 2048
    for (int idx = tid; idx < 2048; idx += 256) {
        int lanep = idx & 31;
        int kb    = (idx >> 5) & 31;
        int nbl   = idx >> 10;            // 0..1
        int pl = nbl * 8 + (lanep >> 2);  // local p row 0..15
        int fb = kb * 16 + (lanep & 3) * 2;
        uint2 w1, w2;
#pragma unroll
        for (int r = 0; r < 2; r++) {
            float acc0 = Outs[pl * F_SZ + fb + r * 8];
            float acc1 = Outs[pl * F_SZ + fb + r * 8 + 1];
            float pp0 = fmaxf(acc0, 0.f), pp1 = fmaxf(acc1, 0.f);
            float pw0 = acc0 * pp0, pw1 = acc1 * pp1;
            __nv_bfloat162 v1 = __floats2bfloat162_rn(th * pw0 + a_ * pp0, th * pw1 + a_ * pp1);
            __nv_bfloat162 v2 = __floats2bfloat162_rn(b_ * pw0, b_ * pw1);
            uint32_t u1 = *reinterpret_cast<uint32_t*>(&v1);
            uint32_t u2 = *reinterpret_cast<uint32_t*>(&v2);
            if (r == 0) { w1.x = u1; w2.x = u2; } else { w1.y = u1; w2.y = u2; }
        }
        int nb = blockIdx.x * 2 + nbl;
        size_t off = ((size_t)nb * 32 + kb) * 32 + lanep;
        g_W1p[off] = w1;
        g_W2p[off] = w2;
    }

    for (int r = warp * 2; r < warp * 2 + 2; r++) {
        float s = 0.f;
        for (int cix = lane; cix < F_SZ; cix += 32) {
            float acc = Outs[r * F_SZ + cix];
            s += acc * fmaxf(acc, 0.f);
        }
#pragma unroll
        for (int o = 16; o > 0; o >>= 1) s += __shfl_xor_sync(0xffffffffu, s, o);
        if (lane == 0) g_biasP[p0 + r] = -b_ * s;
    }
}

// ===================== kernel 2: fused, 64-row CTAs, 2 CTA/SM =====================
#define RS_BYTES   (64 * RS_LD * 2)                  // 66,560
#define BUF_OFF    RS_BYTES
#define STWP_OFF   (BUF_OFF + 34048)
#define BUF_BYTES  (34048 + 8192)
#define RB_OFF     (BUF_OFF + BUF_BYTES)
#define BP_OFF     (RB_OFF + 256)
#define SMEM_FUSED (BP_OFF + 1024)                   // ≈ 107 KB

__global__ __launch_bounds__(256, 2)
void fused_kernel(const float* __restrict__ x,
                  const float* __restrict__ alpha,
                  float* __restrict__ out) {
    extern __shared__ char smraw[];
    __nv_bfloat16* Rs = (__nv_bfloat16*)smraw;
    float*         rb = (float*)(smraw + RB_OFF);
    float*         bp = (float*)(smraw + BP_OFF);

    int tid  = threadIdx.x;
    int warp = tid >> 5;
    int lane = tid & 31;
    int m0   = blockIdx.x * 64;

    // ---------------- Phase A: R = relu(x @ F^T), fp16 wmma, two f-passes ----------------
    using FA1 = wmma::fragment<wmma::matrix_a, 16, 16, 16, __half, wmma::row_major>;
    using FB1 = wmma::fragment<wmma::matrix_b, 16, 16, 16, __half, wmma::col_major>;
    using FC1 = wmma::fragment<wmma::accumulator, 16, 16, 16, float>;

    __half* xs = (__half*)(smraw + BUF_OFF);   // [64][XS_LD] fp16, whole K resident
    {
        const float4* src = (const float4*)(x + (size_t)m0 * D_SZ);
        for (int i = tid; i < 64 * 64; i += 256) {
            int row = i >> 6, q = i & 63;
            float4 v = src[(size_t)row * 64 + q];
            __half2 h0 = __floats2half2_rn(v.x, v.y);
            __half2 h1 = __floats2half2_rn(v.z, v.w);
            uint2 w;
            w.x = *reinterpret_cast<uint32_t*>(&h0);
            w.y = *reinterpret_cast<uint32_t*>(&h1);
            *(uint2*)(xs + row * XS_LD + q * 4) = w;
        }
    }
    __syncthreads();

    for (int fpass = 0; fpass < 2; fpass++) {
        FC1 c[4][2];
#pragma unroll
        for (int i = 0; i < 4; i++)
#pragma unroll
            for (int j = 0; j < 2; j++) wmma::fill_fragment(c[i][j], 0.f);

        int f0 = fpass * 256 + warp * 32;

#pragma unroll 2
        for (int k0 = 0; k0 < D_SZ; k0 += 16) {
            FA1 a[4];
#pragma unroll
            for (int i = 0; i < 4; i++)
                wmma::load_matrix_sync(a[i], xs + (i * 16) * XS_LD + k0, XS_LD);
#pragma unroll
            for (int j = 0; j < 2; j++) {
                FB1 b;
                wmma::load_matrix_sync(b, g_Fh + (size_t)(f0 + j * 16) * D_SZ + k0, D_SZ);
#pragma unroll
                for (int i = 0; i < 4; i++) wmma::mma_sync(c[i][j], a[i], b, c[i][j]);
            }
        }

        float* stw = (float*)(smraw + STWP_OFF) + warp * 256;
#pragma unroll
        for (int i = 0; i < 4; i++) {
#pragma unroll
            for (int j = 0; j < 2; j++) {
                wmma::store_matrix_sync(stw, c[i][j], 16, wmma::mem_row_major);
                __syncwarp();
#pragma unroll
                for (int e = 0; e < 8; e++) {
                    int idx = lane * 8 + e;
                    int rr = idx >> 4, cc = idx & 15;
                    float v = fmaxf(stw[idx], 0.f);
                    Rs[(i * 16 + rr) * RS_LD + f0 + j * 16 + cc] = __float2bfloat16(v);
                }
                __syncwarp();
            }
        }
    }
    __syncthreads();   // Rs complete; xs/stw dead

    // row bias
    {
        float av = alpha[0];
        for (int r = warp * 8; r < warp * 8 + 8; r++) {
            float s = 0.f;
            for (int cix = lane; cix < F_SZ; cix += 32) {
                float v = __bfloat162float(Rs[r * RS_LD + cix]);
                s += v * v;
            }
#pragma unroll
            for (int o = 16; o > 0; o >>= 1) s += __shfl_xor_sync(0xffffffffu, s, o);
            if (lane == 0) rb[r] = -av * s;
        }
    }
    if (tid < P_SZ) bp[tid] = g_biasP[tid];

    // ---------------- Phase B: raw mma.sync m16n8k16, 64x32 warp tiles ----------------
    // A from Rs via ldmatrix.x4; B fragments via coalesced LDG.64 from packed g_W{1,2}p.
    // Per k-step: mma(R, W2) then square A in-register (bf16x2 mul) then mma(R^2, W1).
    float c2[4][4][4];
#pragma unroll
    for (int i = 0; i < 4; i++)
#pragma unroll
        for (int j = 0; j < 4; j++)
#pragma unroll
            for (int e = 0; e < 4; e++) c2[i][j][e] = 0.f;

    const uint32_t su_rs = smem_u32(Rs);
    const int mtx = lane >> 3, mrw = lane & 7;
    // ldmatrix lane address components: matrix mtx, row mrw
    const uint32_t arow_off = (uint32_t)(((mtx & 1) * 8 + mrw) * (RS_LD * 2) + (mtx >> 1) * 16);

#pragma unroll 4
    for (int kk = 0; kk < 32; kk++) {
        uint2 b1r[4], b2r[4];
#pragma unroll
        for (int j = 0; j < 4; j++) {
            size_t off = ((size_t)(warp * 4 + j) * 32 + kk) * 32 + lane;
            b1r[j] = g_W1p[off];
            b2r[j] = g_W2p[off];
        }
#pragma unroll
        for (int i = 0; i < 4; i++) {
            uint32_t a0, a1, a2, a3;
            uint32_t addr = su_rs + (uint32_t)(i * 16 * RS_LD * 2 + kk * 32) + arow_off;
            asm volatile("ldmatrix.sync.aligned.m8n8.x4.shared.b16 {%0,%1,%2,%3}, [%4];"
                         : "=r"(a0), "=r"(a1), "=r"(a2), "=r"(a3) : "r"(addr));
#pragma unroll
            for (int j = 0; j < 4; j++)
                asm volatile("mma.sync.aligned.m16n8k16.row.col.f32.bf16.bf16.f32 "
                             "{%0,%1,%2,%3}, {%4,%5,%6,%7}, {%8,%9}, {%0,%1,%2,%3};"
                             : "+f"(c2[i][j][0]), "+f"(c2[i][j][1]),
                               "+f"(c2[i][j][2]), "+f"(c2[i][j][3])
                             : "r"(a0), "r"(a1), "r"(a2), "r"(a3),
                               "r"(b2r[j].x), "r"(b2r[j].y));
            // square A in bf16 (same numerics as fragment-wise bf16 multiply)
            {
                __nv_bfloat162* p0 = reinterpret_cast<__nv_bfloat162*>(&a0);
                __nv_bfloat162* p1 = reinterpret_cast<__nv_bfloat162*>(&a1);
                __nv_bfloat162* p2 = reinterpret_cast<__nv_bfloat162*>(&a2);
                __nv_bfloat162* p3 = reinterpret_cast<__nv_bfloat162*>(&a3);
                *p0 = __hmul2(*p0, *p0); *p1 = __hmul2(*p1, *p1);
                *p2 = __hmul2(*p2, *p2); *p3 = __hmul2(*p3, *p3);
            }
#pragma unroll
            for (int j = 0; j < 4; j++)
                asm volatile("mma.sync.aligned.m16n8k16.row.col.f32.bf16.bf16.f32 "
                             "{%0,%1,%2,%3}, {%4,%5,%6,%7}, {%8,%9}, {%0,%1,%2,%3};"
                             : "+f"(c2[i][j][0]), "+f"(c2[i][j][1]),
                               "+f"(c2[i][j][2]), "+f"(c2[i][j][3])
                             : "r"(a0), "r"(a1), "r"(a2), "r"(a3),
                               "r"(b1r[j].x), "r"(b1r[j].y));
        }
    }
    __syncthreads();   // all warps done reading Rs -> Os takes over

    float* Os = (float*)smraw;   // [64][OS_LD] fp32
    {
        int ncol = warp * 32;
        int r0 = lane >> 2;
        int cofs = (lane & 3) * 2;
#pragma unroll
        for (int i = 0; i < 4; i++)
#pragma unroll
            for (int j = 0; j < 4; j++) {
                int col = ncol + j * 8 + cofs;
                *(float2*)(Os + (i * 16 + r0) * OS_LD + col)     = make_float2(c2[i][j][0], c2[i][j][1]);
                *(float2*)(Os + (i * 16 + r0 + 8) * OS_LD + col) = make_float2(c2[i][j][2], c2[i][j][3]);
            }
    }
    __syncthreads();

    for (int i = tid; i < 64 * P_SZ; i += 256) {
        int r = i >> 8;
        int p = i & 255;
        out[(size_t)(m0 + r) * P_SZ + p] = Os[r * OS_LD + p] + rb[r] + bp[p];
    }
}

// =========================== launch ===========================
extern "C" void kernel_launch(void* const* d_in, const int* in_sizes, int n_in,
                              void* d_out, int out_size) {
    const float* x          = (const float*)d_in[0];
    const float* features   = (const float*)d_in[1];
    const float* prototypes = (const float*)d_in[2];
    const float* alpha      = (const float*)d_in[3];
    const float* beta       = (const float*)d_in[4];
    const float* theta      = (const float*)d_in[5];
    float* out = (float*)d_out;

    cudaFuncSetAttribute(pside_kernel, cudaFuncAttributeMaxDynamicSharedMemorySize, 64 * 1024);
    cudaFuncSetAttribute(fused_kernel, cudaFuncAttributeMaxDynamicSharedMemorySize, SMEM_FUSED);

    fconv_kernel<<<F_SZ * D_SZ / 4 / 256, 256>>>(features);
    pside_kernel<<<P_SZ / 16, 256, 64 * 1024>>>(prototypes, features, alpha, beta, theta);
    fused_kernel<<<B_SZ / 64, 256, SMEM_FUSED>>>(x, alpha, out);
}